// round 6
// baseline (speedup 1.0000x reference)
#include <cuda_runtime.h>
#include <math.h>

// ---------------- problem constants ----------------
#define TT      4000          // N_WORDS (sequence length)
#define NCHARS  16000
#define DCHAR   768
#define HH      400           // hidden size
#define KCTA    50            // CTAs per LSTM direction
#define HS      8             // h elements per CTA (one per compute warp)
#define NT      384           // 8 compute warps + 4 poller warps

// ---------------- device scratch (static, no allocation) ----------------
__device__ float g_ef[TT * 868];        // [wc(768) | pos(100)]
__device__ float g_l1[TT * 800];        // layer-1 output [f1 | flip(f2)]
__device__ float g_PF[TT * 1600];       // x-projection, forward dir
__device__ float g_PB[TT * 1600];       // x-projection, backward dir
__device__ float g_mean[TT * DCHAR];    // chars_mean
// tagged h broadcast: 4 sets (F1,B1,F2,B2) x 2 parities x 400 elements
__device__ __align__(16) unsigned long long g_hb[4 * 2 * HH];

// ---------------- k_mean: binary-search starts + segment mean + zero g_hb ----
__global__ void k_mean(const float* __restrict__ chem, const int* __restrict__ seg) {
    int w = blockIdx.x, tid = threadIdx.x;
    if (w < 13) {                       // fold in: zero broadcast buffers
        int i = w * 256 + tid;
        if (i < 4 * 2 * HH) g_hb[i] = 0ULL;
    }
    __shared__ int se[2];
    if (tid < 2) {
        int target = w + tid;           // lower_bound(seg, target)
        int lo = 0, hi = NCHARS;
        while (lo < hi) { int m = (lo + hi) >> 1; if (seg[m] < target) lo = m + 1; else hi = m; }
        se[tid] = lo;
    }
    __syncthreads();
    int s = se[0], e = se[1];
    float inv = 1.f / (float)(e - s);
    for (int d = tid; d < DCHAR; d += blockDim.x) {
        float acc = 0.f;
        for (int r = s; r < e; r++) acc += chem[(size_t)(r + 1) * DCHAR + d];
        g_mean[(size_t)w * DCHAR + d] = acc * inv;
    }
}

// ---------------- fp32 GEMM: C[m,n] = dot(A[m,:], B[n,:]) + bias[n] ----------------
__global__ void __launch_bounds__(256, 2) k_gemm(
    int M, int N, int Ka,
    const float* __restrict__ A, int lda, const int* __restrict__ Aidx,
    const float* __restrict__ B0, const float* __restrict__ bias0, float* __restrict__ C0,
    const float* __restrict__ B1, const float* __restrict__ bias1, float* __restrict__ C1,
    int ldc, const float* __restrict__ extra, int mode,
    const int* __restrict__ pos_seq, const float* __restrict__ pos_table)
{
    if (mode == 1 && blockIdx.z == 1) {
        int nb = gridDim.x * gridDim.y;
        int bid = blockIdx.y * gridDim.x + blockIdx.x;
        for (int i = bid * 256 + threadIdx.x; i < TT * 100; i += nb * 256) {
            int m = i / 100, j = i - m * 100;
            g_ef[(size_t)m * 868 + 768 + j] = pos_table[pos_seq[m] * 100 + j];
        }
        return;
    }
    const float* B    = blockIdx.z ? B1    : B0;
    const float* bias = blockIdx.z ? bias1 : bias0;
    float*       C    = blockIdx.z ? C1    : C0;

    __shared__ float As[16][132];
    __shared__ float Bs[16][132];
    int tid = threadIdx.x;
    int tx = tid & 15, ty = tid >> 4;
    int m0 = blockIdx.y * 128, n0 = blockIdx.x * 128;
    int lr = tid >> 2;
    int lk = (tid & 3) * 4;

    float acc[8][8];
#pragma unroll
    for (int i = 0; i < 8; i++)
#pragma unroll
        for (int j = 0; j < 8; j++) acc[i][j] = 0.f;

    for (int kt = 0; kt < Ka; kt += 16) {
#pragma unroll
        for (int p = 0; p < 2; p++) {
            int m = lr + p * 64; int gm = m0 + m;
            float4 v = make_float4(0.f, 0.f, 0.f, 0.f);
            if (gm < M && kt + lk < Ka) {
                int ar = Aidx ? Aidx[gm] : gm;
                v = *(const float4*)&A[(size_t)ar * lda + kt + lk];
            }
            As[lk + 0][m] = v.x; As[lk + 1][m] = v.y;
            As[lk + 2][m] = v.z; As[lk + 3][m] = v.w;
        }
#pragma unroll
        for (int p = 0; p < 2; p++) {
            int n = lr + p * 64; int gn = n0 + n;
            float4 v = make_float4(0.f, 0.f, 0.f, 0.f);
            if (gn < N && kt + lk < Ka) {
                v = *(const float4*)&B[(size_t)gn * Ka + kt + lk];
            }
            Bs[lk + 0][n] = v.x; Bs[lk + 1][n] = v.y;
            Bs[lk + 2][n] = v.z; Bs[lk + 3][n] = v.w;
        }
        __syncthreads();
#pragma unroll
        for (int kk = 0; kk < 16; kk++) {
            float a[8], b[8];
            *(float4*)&a[0] = *(const float4*)&As[kk][ty * 8];
            *(float4*)&a[4] = *(const float4*)&As[kk][ty * 8 + 4];
            *(float4*)&b[0] = *(const float4*)&Bs[kk][tx * 8];
            *(float4*)&b[4] = *(const float4*)&Bs[kk][tx * 8 + 4];
#pragma unroll
            for (int i = 0; i < 8; i++)
#pragma unroll
                for (int j = 0; j < 8; j++) acc[i][j] += a[i] * b[j];
        }
        __syncthreads();
    }
#pragma unroll
    for (int i = 0; i < 8; i++) {
        int m = m0 + ty * 8 + i;
        if (m < M) {
#pragma unroll
            for (int j = 0; j < 8; j++) {
                int n = n0 + tx * 8 + j;
                if (n < N) {
                    float v = acc[i][j] + bias[n];
                    if (mode == 1) v = tanhf(v) + extra[(size_t)m * DCHAR + n];
                    C[(size_t)m * ldc + n] = v;
                }
            }
        }
    }
}

// ---------------- persistent bidirectional LSTM recurrence ----------------
// Compute warp w (w<8) owns hidden element e = k*8 + w. Lane layout: lane =
// q*8+p (q = gate, p = k-slice). Each lane does a 52-wide float4 dot for its
// gate row, 3-stage butterfly within the 8-lane group, then 3 independent
// shfl_xor exchange the 4 gate sums; ALL lanes redundantly compute c,h; lane
// 0 publishes the tagged packet to L2 first, then the layer output.
// Warps 8-11: 100 poller threads x 4 elements, polling from step start with
// 4 concurrent relaxed loads; they fill the next h smem buffer.
__global__ void __launch_bounds__(NT, 1) k_lstm(
    const float* __restrict__ Pf, const float* __restrict__ Whhf,
    const float* __restrict__ h0f, const float* __restrict__ c0f,
    float* outf, int ldf, int colf, int flinf, int floutf, unsigned long long* hbf,
    const float* __restrict__ Pb, const float* __restrict__ Whhb,
    const float* __restrict__ h0b, const float* __restrict__ c0b,
    float* outb, int ldb, int colb, int flinb, int floutb, unsigned long long* hbb)
{
    int dir = blockIdx.x >= KCTA;
    int k   = blockIdx.x - dir * KCTA;
    const float* P   = dir ? Pb   : Pf;
    const float* Whh = dir ? Whhb : Whhf;
    const float* h0  = dir ? h0b  : h0f;
    const float* c0  = dir ? c0b  : c0f;
    float* outbase   = dir ? outb : outf;
    int ld    = dir ? ldb    : ldf;
    int col   = dir ? colb   : colf;
    int flin  = dir ? flinb  : flinf;
    int flout = dir ? floutb : floutf;
    unsigned long long* hb = dir ? hbb : hbf;

    __shared__ __align__(16) float hbuf[2][416];   // double-buffered h (tail zero)

    int tid = threadIdx.x, lane = tid & 31, w = tid >> 5;

    for (int i = tid; i < 416; i += NT) {
        hbuf[0][i] = (i < HH) ? h0[i] : 0.f;
        hbuf[1][i] = 0.f;
    }

    if (w < 8) {
        // ---------------- compute warp ----------------
        int e = k * HS + w;
        int q = lane >> 3, p = lane & 7;

        float creg = c0[e];     // replicated on all lanes

        // 13 float4 weight chunks of gate-row q for element e
        float4 wv[13];
        {
            const float* wp = Whh + (size_t)(q * HH + e) * HH;
#pragma unroll
            for (int j = 0; j < 13; j++) {
                int c0i = (p * 13 + j) * 4;
                float4 v;
                v.x = (c0i + 0 < HH) ? wp[c0i + 0] : 0.f;
                v.y = (c0i + 1 < HH) ? wp[c0i + 1] : 0.f;
                v.z = (c0i + 2 < HH) ? wp[c0i + 2] : 0.f;
                v.w = (c0i + 3 < HH) ? wp[c0i + 3] : 0.f;
                wv[j] = v;
            }
        }

        // x-projection for step 0 (every lane loads its own gate's term)
        float xcur;
        {
            int row = flin ? (TT - 1) : 0;
            xcur = P[(size_t)row * 1600 + q * HH + e];
        }
        __syncthreads();

        for (int s = 0; s < TT; s++) {
            // prefetch next step's x (one full step of slack)
            float xn = 0.f;
            if (s + 1 < TT) {
                int row = flin ? (TT - 2 - s) : (s + 1);
                xn = P[(size_t)row * 1600 + q * HH + e];
            }

            const float4* cur4 = (const float4*)hbuf[s & 1];

            // 52-wide dot for gate row q (4 parallel accumulator chains)
            float ax = 0.f, ay = 0.f, az = 0.f, aw = 0.f;
#pragma unroll
            for (int j = 0; j < 13; j++) {
                float4 hv = cur4[p * 13 + j];
                ax += wv[j].x * hv.x;
                ay += wv[j].y * hv.y;
                az += wv[j].z * hv.z;
                aw += wv[j].w * hv.w;
            }
            float a = (ax + ay) + (az + aw);
            // butterfly within the 8-lane p-group
            a += __shfl_xor_sync(0xffffffffu, a, 4);
            a += __shfl_xor_sync(0xffffffffu, a, 2);
            a += __shfl_xor_sync(0xffffffffu, a, 1);

            // gate nonlinearity (tanh for q==2, sigmoid otherwise)
            float z = a + xcur;
            float earg = (q == 2) ? (-2.f * z) : (-z);
            float r = 1.f / (1.f + __expf(earg));
            float nl = (q == 2) ? (2.f * r - 1.f) : r;

            // exchange the 4 gate values (3 independent shfls)
            float v1 = __shfl_xor_sync(0xffffffffu, nl, 8);
            float v2 = __shfl_xor_sync(0xffffffffu, nl, 16);
            float v3 = __shfl_xor_sync(0xffffffffu, nl, 24);
            // gate g lives in v[q ^ g]
            float gi = (q == 0) ? nl : (q == 1) ? v1 : (q == 2) ? v2 : v3;
            float gf = (q == 0) ? v1 : (q == 1) ? nl : (q == 2) ? v3 : v2;
            float gg = (q == 0) ? v2 : (q == 1) ? v3 : (q == 2) ? nl : v1;
            float go = (q == 0) ? v3 : (q == 1) ? v2 : (q == 2) ? v1 : nl;

            float c = gf * creg + gi * gg;
            creg = c;
            float th = 2.f / (1.f + __expf(-2.f * c)) - 1.f;
            float h = go * th;

            int orow = flout ? (TT - 1 - s) : s;
            if (lane == 0) {
                if (s + 1 < TT) {       // publish FIRST (starts visibility clock)
                    unsigned long long pk =
                        ((unsigned long long)(unsigned)(s + 1) << 32) |
                        (unsigned long long)__float_as_uint(h);
                    unsigned long long* dst = hb + (size_t)(s & 1) * HH + e;
                    asm volatile("st.relaxed.gpu.global.b64 [%0], %1;"
                                 :: "l"(dst), "l"(pk) : "memory");
                }
                outbase[(size_t)orow * ld + col + e] = h;
            }
            xcur = xn;
            __syncthreads();
        }
    } else {
        // ---------------- poller warps ----------------
        int t = tid - 256;              // 0..127, active if t < 100
        unsigned long long* myhb = hb + 4 * t;
        float* nxt0 = hbuf[1];          // next buffer for even s is hbuf[1]
        __syncthreads();
        for (int s = 0; s < TT; s++) {
            if (s + 1 < TT && t < 100) {
                const unsigned long long* sp = myhb + (size_t)(s & 1) * HH;
                float* nxt = hbuf[(s + 1) & 1];
                unsigned tgt = (unsigned)(s + 1);
                unsigned long long v0, v1, v2, v3;
                for (;;) {
                    asm volatile(
                        "ld.relaxed.gpu.global.b64 %0, [%4];\n\t"
                        "ld.relaxed.gpu.global.b64 %1, [%4+8];\n\t"
                        "ld.relaxed.gpu.global.b64 %2, [%4+16];\n\t"
                        "ld.relaxed.gpu.global.b64 %3, [%4+24];"
                        : "=l"(v0), "=l"(v1), "=l"(v2), "=l"(v3)
                        : "l"(sp) : "memory");
                    if ((unsigned)(v0 >> 32) == tgt && (unsigned)(v1 >> 32) == tgt &&
                        (unsigned)(v2 >> 32) == tgt && (unsigned)(v3 >> 32) == tgt) break;
                }
                nxt[4 * t + 0] = __uint_as_float((unsigned)v0);
                nxt[4 * t + 1] = __uint_as_float((unsigned)v1);
                nxt[4 * t + 2] = __uint_as_float((unsigned)v2);
                nxt[4 * t + 3] = __uint_as_float((unsigned)v3);
            }
            __syncthreads();
        }
        (void)nxt0;
    }
}

// ---------------- launch ----------------
extern "C" void kernel_launch(void* const* d_in, const int* in_sizes, int n_in,
                              void* d_out, int out_size)
{
    const int*   word_seq   = (const int*)  d_in[0];
    const int*   pos_seq    = (const int*)  d_in[1];
    const int*   seg_ids    = (const int*)  d_in[2];
    const float* chem       = (const float*)d_in[3];
    const float* word_table = (const float*)d_in[4];
    const float* pos_table  = (const float*)d_in[5];
    const float* Ww         = (const float*)d_in[6];
    const float* Wb         = (const float*)d_in[7];
    const float* Wih1f = (const float*)d_in[8];
    const float* Whh1f = (const float*)d_in[9];
    const float* b1f   = (const float*)d_in[10];
    const float* h01f  = (const float*)d_in[11];
    const float* c01f  = (const float*)d_in[12];
    const float* Wih1b = (const float*)d_in[13];
    const float* Whh1b = (const float*)d_in[14];
    const float* b1b   = (const float*)d_in[15];
    const float* h01b  = (const float*)d_in[16];
    const float* c01b  = (const float*)d_in[17];
    const float* Wih2f = (const float*)d_in[18];
    const float* Whh2f = (const float*)d_in[19];
    const float* b2f   = (const float*)d_in[20];
    const float* h02f  = (const float*)d_in[21];
    const float* c02f  = (const float*)d_in[22];
    const float* Wih2b = (const float*)d_in[23];
    const float* Whh2b = (const float*)d_in[24];
    const float* b2b   = (const float*)d_in[25];
    const float* h02b  = (const float*)d_in[26];
    const float* c02b  = (const float*)d_in[27];

    float* out = (float*)d_out;

    float *ef, *l1, *PF, *PB, *meanp; unsigned long long* hb;
    cudaGetSymbolAddress((void**)&ef,    g_ef);
    cudaGetSymbolAddress((void**)&l1,    g_l1);
    cudaGetSymbolAddress((void**)&PF,    g_PF);
    cudaGetSymbolAddress((void**)&PB,    g_PB);
    cudaGetSymbolAddress((void**)&meanp, g_mean);
    cudaGetSymbolAddress((void**)&hb,    g_hb);

    // (0) mean + starts(bsearch) + hb zero
    k_mean<<<TT, 256>>>(chem, seg_ids);

    // (1) wc = tanh(word_e @ Ww.T + Wb) + mean -> ef[:, :768]; z=1 blocks do pos fill
    k_gemm<<<dim3(6, 32, 2), 256>>>(TT, 768, 300,
        word_table, 300, word_seq,
        Ww, Wb, ef, nullptr, nullptr, nullptr,
        868, meanp, 1, pos_seq, pos_table);

    // (2) layer-1 input projections (both directions)
    k_gemm<<<dim3(13, 32, 2), 256>>>(TT, 1600, 868,
        ef, 868, nullptr,
        Wih1f, b1f, PF,
        Wih1b, b1b, PB,
        1600, nullptr, 0, nullptr, nullptr);

    // (3) layer-1 recurrence
    k_lstm<<<2 * KCTA, NT>>>(
        PF, Whh1f, h01f, c01f, l1, 800, 0,   0, 0, hb + 0 * 2 * HH,
        PB, Whh1b, h01b, c01b, l1, 800, 400, 1, 1, hb + 1 * 2 * HH);

    // (4) layer-2 input projections on l1
    k_gemm<<<dim3(13, 32, 2), 256>>>(TT, 1600, 800,
        l1, 800, nullptr,
        Wih2f, b2f, PF,
        Wih2b, b2b, PB,
        1600, nullptr, 0, nullptr, nullptr);

    // (5) layer-2 recurrence
    k_lstm<<<2 * KCTA, NT>>>(
        PF, Whh2f, h02f, c02f, out,                    400, 0, 0, 0, hb + 2 * 2 * HH,
        PB, Whh2b, h02b, c02b, out + (size_t)TT * 400, 400, 0, 1, 0, hb + 3 * 2 * HH);
}

// round 7
// speedup vs baseline: 1.3998x; 1.3998x over previous
#include <cuda_runtime.h>
#include <math.h>

// ---------------- problem constants ----------------
#define TT      4000          // N_WORDS (sequence length)
#define NCHARS  16000
#define DCHAR   768
#define HH      400           // hidden size
#define KCTA    50            // CTAs per LSTM direction
#define HS      8             // h elements per CTA (one per warp)
#define NT      256           // threads per CTA

// ---------------- device scratch (static, no allocation) ----------------
__device__ float g_ef[TT * 868];        // [wc(768) | pos(100)]
__device__ float g_l1[TT * 800];        // layer-1 output [f1 | flip(f2)]
__device__ float g_PF[TT * 1600];       // x-projection, forward dir
__device__ float g_PB[TT * 1600];       // x-projection, backward dir
__device__ float g_mean[TT * DCHAR];    // chars_mean
// tagged h broadcast: 4 sets (F1,B1,F2,B2) x 2 parities x 400 elements
__device__ __align__(16) unsigned long long g_hb[4 * 2 * HH];

// ---------------- k_mean: binary-search starts + segment mean + zero g_hb ----
__global__ void k_mean(const float* __restrict__ chem, const int* __restrict__ seg) {
    int w = blockIdx.x, tid = threadIdx.x;
    if (w < 13) {                       // fold in: zero broadcast buffers
        int i = w * 256 + tid;
        if (i < 4 * 2 * HH) g_hb[i] = 0ULL;
    }
    __shared__ int se[2];
    if (tid < 2) {
        int target = w + tid;           // lower_bound(seg, target)
        int lo = 0, hi = NCHARS;
        while (lo < hi) { int m = (lo + hi) >> 1; if (seg[m] < target) lo = m + 1; else hi = m; }
        se[tid] = lo;
    }
    __syncthreads();
    int s = se[0], e = se[1];
    float inv = 1.f / (float)(e - s);
    for (int d = tid; d < DCHAR; d += blockDim.x) {
        float acc = 0.f;
        for (int r = s; r < e; r++) acc += chem[(size_t)(r + 1) * DCHAR + d];
        g_mean[(size_t)w * DCHAR + d] = acc * inv;
    }
}

// ---------------- fp32 GEMM: C[m,n] = dot(A[m,:], B[n,:]) + bias[n] ----------------
__global__ void __launch_bounds__(256, 2) k_gemm(
    int M, int N, int Ka,
    const float* __restrict__ A, int lda, const int* __restrict__ Aidx,
    const float* __restrict__ B0, const float* __restrict__ bias0, float* __restrict__ C0,
    const float* __restrict__ B1, const float* __restrict__ bias1, float* __restrict__ C1,
    int ldc, const float* __restrict__ extra, int mode,
    const int* __restrict__ pos_seq, const float* __restrict__ pos_table)
{
    if (mode == 1 && blockIdx.z == 1) {
        int nb = gridDim.x * gridDim.y;
        int bid = blockIdx.y * gridDim.x + blockIdx.x;
        for (int i = bid * 256 + threadIdx.x; i < TT * 100; i += nb * 256) {
            int m = i / 100, j = i - m * 100;
            g_ef[(size_t)m * 868 + 768 + j] = pos_table[pos_seq[m] * 100 + j];
        }
        return;
    }
    const float* B    = blockIdx.z ? B1    : B0;
    const float* bias = blockIdx.z ? bias1 : bias0;
    float*       C    = blockIdx.z ? C1    : C0;

    __shared__ float As[16][132];
    __shared__ float Bs[16][132];
    int tid = threadIdx.x;
    int tx = tid & 15, ty = tid >> 4;
    int m0 = blockIdx.y * 128, n0 = blockIdx.x * 128;
    int lr = tid >> 2;
    int lk = (tid & 3) * 4;

    float acc[8][8];
#pragma unroll
    for (int i = 0; i < 8; i++)
#pragma unroll
        for (int j = 0; j < 8; j++) acc[i][j] = 0.f;

    for (int kt = 0; kt < Ka; kt += 16) {
#pragma unroll
        for (int p = 0; p < 2; p++) {
            int m = lr + p * 64; int gm = m0 + m;
            float4 v = make_float4(0.f, 0.f, 0.f, 0.f);
            if (gm < M && kt + lk < Ka) {
                int ar = Aidx ? Aidx[gm] : gm;
                v = *(const float4*)&A[(size_t)ar * lda + kt + lk];
            }
            As[lk + 0][m] = v.x; As[lk + 1][m] = v.y;
            As[lk + 2][m] = v.z; As[lk + 3][m] = v.w;
        }
#pragma unroll
        for (int p = 0; p < 2; p++) {
            int n = lr + p * 64; int gn = n0 + n;
            float4 v = make_float4(0.f, 0.f, 0.f, 0.f);
            if (gn < N && kt + lk < Ka) {
                v = *(const float4*)&B[(size_t)gn * Ka + kt + lk];
            }
            Bs[lk + 0][n] = v.x; Bs[lk + 1][n] = v.y;
            Bs[lk + 2][n] = v.z; Bs[lk + 3][n] = v.w;
        }
        __syncthreads();
#pragma unroll
        for (int kk = 0; kk < 16; kk++) {
            float a[8], b[8];
            *(float4*)&a[0] = *(const float4*)&As[kk][ty * 8];
            *(float4*)&a[4] = *(const float4*)&As[kk][ty * 8 + 4];
            *(float4*)&b[0] = *(const float4*)&Bs[kk][tx * 8];
            *(float4*)&b[4] = *(const float4*)&Bs[kk][tx * 8 + 4];
#pragma unroll
            for (int i = 0; i < 8; i++)
#pragma unroll
                for (int j = 0; j < 8; j++) acc[i][j] += a[i] * b[j];
        }
        __syncthreads();
    }
#pragma unroll
    for (int i = 0; i < 8; i++) {
        int m = m0 + ty * 8 + i;
        if (m < M) {
#pragma unroll
            for (int j = 0; j < 8; j++) {
                int n = n0 + tx * 8 + j;
                if (n < N) {
                    float v = acc[i][j] + bias[n];
                    if (mode == 1) v = tanhf(v) + extra[(size_t)m * DCHAR + n];
                    C[(size_t)m * ldc + n] = v;
                }
            }
        }
    }
}

// ---------------- persistent bidirectional LSTM recurrence ----------------
// Round-4 skeleton (poll-after-compute, same threads — self-throttling, no
// arbiter starvation) + shallow datapath: warp w owns element e = k*8 + w,
// lane = q*8+p (q = gate, p = k-slice). Each lane: 52-wide float4 dot for
// gate row q, 3-stage butterfly in the p-group, gate nonlinearity, 3
// independent shfl_xor to exchange the 4 gates; all lanes form c,h; lane 0
// publishes the tagged packet FIRST, then the layer output. Afterwards
// threads 0..199 poll 2 elements each (own CTA slice skipped).
__global__ void __launch_bounds__(NT, 1) k_lstm(
    const float* __restrict__ Pf, const float* __restrict__ Whhf,
    const float* __restrict__ h0f, const float* __restrict__ c0f,
    float* outf, int ldf, int colf, int flinf, int floutf, unsigned long long* hbf,
    const float* __restrict__ Pb, const float* __restrict__ Whhb,
    const float* __restrict__ h0b, const float* __restrict__ c0b,
    float* outb, int ldb, int colb, int flinb, int floutb, unsigned long long* hbb)
{
    int dir = blockIdx.x >= KCTA;
    int k   = blockIdx.x - dir * KCTA;
    const float* P   = dir ? Pb   : Pf;
    const float* Whh = dir ? Whhb : Whhf;
    const float* h0  = dir ? h0b  : h0f;
    const float* c0  = dir ? c0b  : c0f;
    float* outbase   = dir ? outb : outf;
    int ld    = dir ? ldb    : ldf;
    int col   = dir ? colb   : colf;
    int flin  = dir ? flinb  : flinf;
    int flout = dir ? floutb : floutf;
    unsigned long long* hb = dir ? hbb : hbf;

    __shared__ __align__(16) float hbuf[2][416];   // double-buffered h (tail zero)

    int tid = threadIdx.x, lane = tid & 31, w = tid >> 5;
    int e = k * HS + w;              // hidden element owned by this warp
    int q = lane >> 3, p = lane & 7; // gate, k-slice

    for (int i = tid; i < 416; i += NT) {
        hbuf[0][i] = (i < HH) ? h0[i] : 0.f;
        hbuf[1][i] = 0.f;
    }
    float creg = c0[e];              // replicated across lanes

    // 13 float4 chunks of gate-row q for element e (zero-padded past 400)
    float4 wv[13];
    {
        const float* wp = Whh + (size_t)(q * HH + e) * HH;
#pragma unroll
        for (int j = 0; j < 13; j++) {
            int ci = (p * 13 + j) * 4;
            float4 v;
            v.x = (ci + 0 < HH) ? wp[ci + 0] : 0.f;
            v.y = (ci + 1 < HH) ? wp[ci + 1] : 0.f;
            v.z = (ci + 2 < HH) ? wp[ci + 2] : 0.f;
            v.w = (ci + 3 < HH) ? wp[ci + 3] : 0.f;
            wv[j] = v;
        }
    }

    // x-projection for step 0 (each lane loads its gate's term; 4 distinct addrs)
    float xcur;
    {
        int row = flin ? (TT - 1) : 0;
        xcur = P[(size_t)row * 1600 + q * HH + e];
    }

    // poller assignment: threads 0..199, 2 elements each; skip own CTA slice
    bool dopoll = (tid < 200) && (tid < k * 4 || tid >= k * 4 + 4);
    __syncthreads();

    for (int s = 0; s < TT; s++) {
        // prefetch next step's x (independent of h — overlaps the GEMV)
        float xn = 0.f;
        if (s + 1 < TT) {
            int row = flin ? (TT - 2 - s) : (s + 1);
            xn = P[(size_t)row * 1600 + q * HH + e];
        }

        const float4* cur4 = (const float4*)hbuf[s & 1];
        float* nxt = hbuf[(s + 1) & 1];

        // 52-wide dot for gate row q (4 parallel accumulator chains)
        float ax = 0.f, ay = 0.f, az = 0.f, aw = 0.f;
#pragma unroll
        for (int j = 0; j < 13; j++) {
            float4 hv = cur4[p * 13 + j];
            ax += wv[j].x * hv.x;
            ay += wv[j].y * hv.y;
            az += wv[j].z * hv.z;
            aw += wv[j].w * hv.w;
        }
        float a = (ax + ay) + (az + aw);
        // 3-stage butterfly within the 8-lane p-group
        a += __shfl_xor_sync(0xffffffffu, a, 4);
        a += __shfl_xor_sync(0xffffffffu, a, 2);
        a += __shfl_xor_sync(0xffffffffu, a, 1);

        // gate nonlinearity (tanh for q==2, sigmoid otherwise)
        float z = a + xcur;
        float earg = (q == 2) ? (-2.f * z) : (-z);
        float r = 1.f / (1.f + __expf(earg));
        float nl = (q == 2) ? (2.f * r - 1.f) : r;

        // exchange the 4 gate values (3 independent shfls); gate g is v[q^g]
        float v1 = __shfl_xor_sync(0xffffffffu, nl, 8);
        float v2 = __shfl_xor_sync(0xffffffffu, nl, 16);
        float v3 = __shfl_xor_sync(0xffffffffu, nl, 24);
        float gi = (q == 0) ? nl : (q == 1) ? v1 : (q == 2) ? v2 : v3;
        float gf = (q == 0) ? v1 : (q == 1) ? nl : (q == 2) ? v3 : v2;
        float gg = (q == 0) ? v2 : (q == 1) ? v3 : (q == 2) ? nl : v1;
        float go = (q == 0) ? v3 : (q == 1) ? v2 : (q == 2) ? v1 : nl;

        float c = gf * creg + gi * gg;
        creg = c;
        float th = 2.f / (1.f + __expf(-2.f * c)) - 1.f;
        float h = go * th;

        int orow = flout ? (TT - 1 - s) : s;
        if (lane == 0) {
            if (s + 1 < TT) {           // publish FIRST (starts visibility clock)
                unsigned long long pk =
                    ((unsigned long long)(unsigned)(s + 1) << 32) |
                    (unsigned long long)__float_as_uint(h);
                unsigned long long* dst = hb + (size_t)(s & 1) * HH + e;
                asm volatile("st.relaxed.gpu.global.b64 [%0], %1;"
                             :: "l"(dst), "l"(pk) : "memory");
                nxt[e] = h;             // own slice locally
            }
            outbase[(size_t)orow * ld + col + e] = h;
        }

        // consume: 200 pollers, 2 elements each, both loads in flight
        if (s + 1 < TT && dopoll) {
            const unsigned long long* sp = hb + (size_t)(s & 1) * HH + 2 * tid;
            unsigned tgt = (unsigned)(s + 1);
            unsigned long long v0, vv1;
            for (;;) {
                asm volatile("ld.relaxed.gpu.global.b64 %0, [%2];\n\t"
                             "ld.relaxed.gpu.global.b64 %1, [%2+8];"
                             : "=l"(v0), "=l"(vv1) : "l"(sp) : "memory");
                if ((unsigned)(v0 >> 32) == tgt && (unsigned)(vv1 >> 32) == tgt) break;
            }
            nxt[2 * tid]     = __uint_as_float((unsigned)v0);
            nxt[2 * tid + 1] = __uint_as_float((unsigned)vv1);
        }
        xcur = xn;
        __syncthreads();   // nxt complete before next GEMV
    }
}

// ---------------- launch ----------------
extern "C" void kernel_launch(void* const* d_in, const int* in_sizes, int n_in,
                              void* d_out, int out_size)
{
    const int*   word_seq   = (const int*)  d_in[0];
    const int*   pos_seq    = (const int*)  d_in[1];
    const int*   seg_ids    = (const int*)  d_in[2];
    const float* chem       = (const float*)d_in[3];
    const float* word_table = (const float*)d_in[4];
    const float* pos_table  = (const float*)d_in[5];
    const float* Ww         = (const float*)d_in[6];
    const float* Wb         = (const float*)d_in[7];
    const float* Wih1f = (const float*)d_in[8];
    const float* Whh1f = (const float*)d_in[9];
    const float* b1f   = (const float*)d_in[10];
    const float* h01f  = (const float*)d_in[11];
    const float* c01f  = (const float*)d_in[12];
    const float* Wih1b = (const float*)d_in[13];
    const float* Whh1b = (const float*)d_in[14];
    const float* b1b   = (const float*)d_in[15];
    const float* h01b  = (const float*)d_in[16];
    const float* c01b  = (const float*)d_in[17];
    const float* Wih2f = (const float*)d_in[18];
    const float* Whh2f = (const float*)d_in[19];
    const float* b2f   = (const float*)d_in[20];
    const float* h02f  = (const float*)d_in[21];
    const float* c02f  = (const float*)d_in[22];
    const float* Wih2b = (const float*)d_in[23];
    const float* Whh2b = (const float*)d_in[24];
    const float* b2b   = (const float*)d_in[25];
    const float* h02b  = (const float*)d_in[26];
    const float* c02b  = (const float*)d_in[27];

    float* out = (float*)d_out;

    float *ef, *l1, *PF, *PB, *meanp; unsigned long long* hb;
    cudaGetSymbolAddress((void**)&ef,    g_ef);
    cudaGetSymbolAddress((void**)&l1,    g_l1);
    cudaGetSymbolAddress((void**)&PF,    g_PF);
    cudaGetSymbolAddress((void**)&PB,    g_PB);
    cudaGetSymbolAddress((void**)&meanp, g_mean);
    cudaGetSymbolAddress((void**)&hb,    g_hb);

    // (0) mean + starts(bsearch) + hb zero
    k_mean<<<TT, 256>>>(chem, seg_ids);

    // (1) wc = tanh(word_e @ Ww.T + Wb) + mean -> ef[:, :768]; z=1 blocks do pos fill
    k_gemm<<<dim3(6, 32, 2), 256>>>(TT, 768, 300,
        word_table, 300, word_seq,
        Ww, Wb, ef, nullptr, nullptr, nullptr,
        868, meanp, 1, pos_seq, pos_table);

    // (2) layer-1 input projections (both directions)
    k_gemm<<<dim3(13, 32, 2), 256>>>(TT, 1600, 868,
        ef, 868, nullptr,
        Wih1f, b1f, PF,
        Wih1b, b1b, PB,
        1600, nullptr, 0, nullptr, nullptr);

    // (3) layer-1 recurrence
    k_lstm<<<2 * KCTA, NT>>>(
        PF, Whh1f, h01f, c01f, l1, 800, 0,   0, 0, hb + 0 * 2 * HH,
        PB, Whh1b, h01b, c01b, l1, 800, 400, 1, 1, hb + 1 * 2 * HH);

    // (4) layer-2 input projections on l1
    k_gemm<<<dim3(13, 32, 2), 256>>>(TT, 1600, 800,
        l1, 800, nullptr,
        Wih2f, b2f, PF,
        Wih2b, b2b, PB,
        1600, nullptr, 0, nullptr, nullptr);

    // (5) layer-2 recurrence
    k_lstm<<<2 * KCTA, NT>>>(
        PF, Whh2f, h02f, c02f, out,                    400, 0, 0, 0, hb + 2 * 2 * HH,
        PB, Whh2b, h02b, c02b, out + (size_t)TT * 400, 400, 0, 1, 0, hb + 3 * 2 * HH);
}

// round 11
// speedup vs baseline: 2.5532x; 1.8240x over previous
#include <cuda_runtime.h>
#include <math.h>

// ---------------- problem constants ----------------
#define TT      4000          // N_WORDS (sequence length)
#define NCHARS  16000
#define DCHAR   768
#define HH      400           // hidden size
#define KCTA    50            // CTAs per LSTM direction
#define HS      8             // h elements per CTA (one per warp)
#define NT      256           // threads per CTA

// ---------------- device scratch (static, no allocation) ----------------
__device__ float g_ef[TT * 868];        // [wc(768) | pos(100)]
__device__ float g_l1[TT * 800];        // layer-1 output [f1 | flip(f2)]
__device__ float g_PF[TT * 1600];       // x-projection, forward dir
__device__ float g_PB[TT * 1600];       // x-projection, backward dir
__device__ float g_mean[TT * DCHAR];    // chars_mean
// tagged h broadcast: 4 sets (F1,B1,F2,B2) x 2 parities x 400 elements
__device__ __align__(16) unsigned long long g_hb[4 * 2 * HH];

// ---------------- k_mean: binary-search starts + segment mean + zero g_hb ----
__global__ void k_mean(const float* __restrict__ chem, const int* __restrict__ seg) {
    int w = blockIdx.x, tid = threadIdx.x;
    if (w < 13) {                       // fold in: zero broadcast buffers
        int i = w * 256 + tid;
        if (i < 4 * 2 * HH) g_hb[i] = 0ULL;
    }
    __shared__ int se[2];
    if (tid < 2) {
        int target = w + tid;           // lower_bound(seg, target)
        int lo = 0, hi = NCHARS;
        while (lo < hi) { int m = (lo + hi) >> 1; if (seg[m] < target) lo = m + 1; else hi = m; }
        se[tid] = lo;
    }
    __syncthreads();
    int s = se[0], e = se[1];
    float inv = 1.f / (float)(e - s);
    for (int d = tid; d < DCHAR; d += blockDim.x) {
        float acc = 0.f;
        for (int r = s; r < e; r++) acc += chem[(size_t)(r + 1) * DCHAR + d];
        g_mean[(size_t)w * DCHAR + d] = acc * inv;
    }
}

// ---------------- fp32 GEMM: C[m,n] = dot(A[m,:], B[n,:]) + bias[n] ----------------
// 128x128x16 tiles, 256 threads, 8x8 microtile, float4 loads, register-staged
// double buffering: next k-tile's global loads are issued before computing the
// current tile from smem, so LDG latency hides behind the 1024 FFMAs.
__global__ void __launch_bounds__(256, 2) k_gemm(
    int M, int N, int Ka,
    const float* __restrict__ A, int lda, const int* __restrict__ Aidx,
    const float* __restrict__ B0, const float* __restrict__ bias0, float* __restrict__ C0,
    const float* __restrict__ B1, const float* __restrict__ bias1, float* __restrict__ C1,
    int ldc, const float* __restrict__ extra, int mode,
    const int* __restrict__ pos_seq, const float* __restrict__ pos_table)
{
    if (mode == 1 && blockIdx.z == 1) {
        int nb = gridDim.x * gridDim.y;
        int bid = blockIdx.y * gridDim.x + blockIdx.x;
        for (int i = bid * 256 + threadIdx.x; i < TT * 100; i += nb * 256) {
            int m = i / 100, j = i - m * 100;
            g_ef[(size_t)m * 868 + 768 + j] = pos_table[pos_seq[m] * 100 + j];
        }
        return;
    }
    const float* B    = blockIdx.z ? B1    : B0;
    const float* bias = blockIdx.z ? bias1 : bias0;
    float*       C    = blockIdx.z ? C1    : C0;

    __shared__ float As[16][132];
    __shared__ float Bs[16][132];
    int tid = threadIdx.x;
    int tx = tid & 15, ty = tid >> 4;
    int m0 = blockIdx.y * 128, n0 = blockIdx.x * 128;
    int lr = tid >> 2;          // 0..63
    int lk = (tid & 3) * 4;     // 0,4,8,12

    // resolve A row indices once (gather only for the wc GEMM)
    int arow0, arow1;
    {
        int gm0 = m0 + lr, gm1 = m0 + lr + 64;
        arow0 = (gm0 < M) ? (Aidx ? Aidx[gm0] : gm0) : -1;
        arow1 = (gm1 < M) ? (Aidx ? Aidx[gm1] : gm1) : -1;
    }
    int gn0 = n0 + lr, gn1 = n0 + lr + 64;

    float acc[8][8];
#pragma unroll
    for (int i = 0; i < 8; i++)
#pragma unroll
        for (int j = 0; j < 8; j++) acc[i][j] = 0.f;

    const float4 z4 = make_float4(0.f, 0.f, 0.f, 0.f);

    // ---- prologue: load k-tile 0 into regs, then smem ----
    float4 sa0, sa1, sb0, sb1;
    {
        bool kok = (lk < Ka);
        sa0 = (kok && arow0 >= 0) ? *(const float4*)&A[(size_t)arow0 * lda + lk] : z4;
        sa1 = (kok && arow1 >= 0) ? *(const float4*)&A[(size_t)arow1 * lda + lk] : z4;
        sb0 = (kok && gn0 < N)    ? *(const float4*)&B[(size_t)gn0  * Ka  + lk] : z4;
        sb1 = (kok && gn1 < N)    ? *(const float4*)&B[(size_t)gn1  * Ka  + lk] : z4;
    }
    As[lk + 0][lr] = sa0.x; As[lk + 1][lr] = sa0.y; As[lk + 2][lr] = sa0.z; As[lk + 3][lr] = sa0.w;
    As[lk + 0][lr + 64] = sa1.x; As[lk + 1][lr + 64] = sa1.y; As[lk + 2][lr + 64] = sa1.z; As[lk + 3][lr + 64] = sa1.w;
    Bs[lk + 0][lr] = sb0.x; Bs[lk + 1][lr] = sb0.y; Bs[lk + 2][lr] = sb0.z; Bs[lk + 3][lr] = sb0.w;
    Bs[lk + 0][lr + 64] = sb1.x; Bs[lk + 1][lr + 64] = sb1.y; Bs[lk + 2][lr + 64] = sb1.z; Bs[lk + 3][lr + 64] = sb1.w;
    __syncthreads();

    for (int kt = 0; kt < Ka; kt += 16) {
        int ktn = kt + 16;
        bool more = (ktn < Ka);
        // ---- issue next tile's global loads (latency hidden by compute) ----
        if (more) {
            bool kok = (ktn + lk < Ka);
            sa0 = (kok && arow0 >= 0) ? *(const float4*)&A[(size_t)arow0 * lda + ktn + lk] : z4;
            sa1 = (kok && arow1 >= 0) ? *(const float4*)&A[(size_t)arow1 * lda + ktn + lk] : z4;
            sb0 = (kok && gn0 < N)    ? *(const float4*)&B[(size_t)gn0  * Ka  + ktn + lk] : z4;
            sb1 = (kok && gn1 < N)    ? *(const float4*)&B[(size_t)gn1  * Ka  + ktn + lk] : z4;
        }
        // ---- compute current tile from smem ----
#pragma unroll
        for (int kk = 0; kk < 16; kk++) {
            float a[8], b[8];
            *(float4*)&a[0] = *(const float4*)&As[kk][ty * 8];
            *(float4*)&a[4] = *(const float4*)&As[kk][ty * 8 + 4];
            *(float4*)&b[0] = *(const float4*)&Bs[kk][tx * 8];
            *(float4*)&b[4] = *(const float4*)&Bs[kk][tx * 8 + 4];
#pragma unroll
            for (int i = 0; i < 8; i++)
#pragma unroll
                for (int j = 0; j < 8; j++) acc[i][j] += a[i] * b[j];
        }
        if (more) {
            __syncthreads();
            As[lk + 0][lr] = sa0.x; As[lk + 1][lr] = sa0.y; As[lk + 2][lr] = sa0.z; As[lk + 3][lr] = sa0.w;
            As[lk + 0][lr + 64] = sa1.x; As[lk + 1][lr + 64] = sa1.y; As[lk + 2][lr + 64] = sa1.z; As[lk + 3][lr + 64] = sa1.w;
            Bs[lk + 0][lr] = sb0.x; Bs[lk + 1][lr] = sb0.y; Bs[lk + 2][lr] = sb0.z; Bs[lk + 3][lr] = sb0.w;
            Bs[lk + 0][lr + 64] = sb1.x; Bs[lk + 1][lr + 64] = sb1.y; Bs[lk + 2][lr + 64] = sb1.z; Bs[lk + 3][lr + 64] = sb1.w;
            __syncthreads();
        }
    }
#pragma unroll
    for (int i = 0; i < 8; i++) {
        int m = m0 + ty * 8 + i;
        if (m < M) {
#pragma unroll
            for (int j = 0; j < 8; j++) {
                int n = n0 + tx * 8 + j;
                if (n < N) {
                    float v = acc[i][j] + bias[n];
                    if (mode == 1) v = tanhf(v) + extra[(size_t)m * DCHAR + n];
                    C[(size_t)m * ldc + n] = v;
                }
            }
        }
    }
}

// ---------------- persistent bidirectional LSTM recurrence ----------------
// EXACT round-4 structure (the proven 11.9ms version): warp w owns hidden
// element e = k*8 + w; per-lane 4-gate dot over h[j*32+lane]; 5-stage
// butterfly allreduce; lanes 0-3 apply gate nonlinearities in parallel;
// lane 0 forms (c,h), publishes tagged packet via relaxed L2 store before
// any barrier; threads 0..199 then poll 2 elements each. One bar per step.
__global__ void __launch_bounds__(NT, 1) k_lstm(
    const float* __restrict__ Pf, const float* __restrict__ Whhf,
    const float* __restrict__ h0f, const float* __restrict__ c0f,
    float* outf, int ldf, int colf, int flinf, int floutf, unsigned long long* hbf,
    const float* __restrict__ Pb, const float* __restrict__ Whhb,
    const float* __restrict__ h0b, const float* __restrict__ c0b,
    float* outb, int ldb, int colb, int flinb, int floutb, unsigned long long* hbb)
{
    int dir = blockIdx.x >= KCTA;
    int k   = blockIdx.x - dir * KCTA;
    const float* P   = dir ? Pb   : Pf;
    const float* Whh = dir ? Whhb : Whhf;
    const float* h0  = dir ? h0b  : h0f;
    const float* c0  = dir ? c0b  : c0f;
    float* outbase   = dir ? outb : outf;
    int ld    = dir ? ldb    : ldf;
    int col   = dir ? colb   : colf;
    int flin  = dir ? flinb  : flinf;
    int flout = dir ? floutb : floutf;
    unsigned long long* hb = dir ? hbb : hbf;

    __shared__ float hbuf[2][416];   // double-buffered h (tail zero)

    int tid = threadIdx.x, lane = tid & 31, w = tid >> 5;
    int e = k * HS + w;              // global hidden element owned by this warp

    for (int i = tid; i < 416; i += NT) {
        hbuf[0][i] = (i < HH) ? h0[i] : 0.f;
        hbuf[1][i] = 0.f;
    }
    float creg = 0.f;
    if (lane == 0) creg = c0[e];

    // Whh rows (4 gates of element e) -> registers
    float wreg[4][13];
#pragma unroll
    for (int q = 0; q < 4; q++) {
        const float* wp = Whh + (size_t)(q * HH + e) * HH;
#pragma unroll
        for (int j = 0; j < 13; j++) {
            int cc = j * 32 + lane;
            wreg[q][j] = (cc < HH) ? wp[cc] : 0.f;
        }
    }

    // x-projection for step 0: lane q (q<4) holds gate-q term
    float xcur = 0.f;
    if (lane < 4) {
        int row = flin ? (TT - 1) : 0;
        xcur = P[(size_t)row * 1600 + lane * HH + e];
    }
    __syncthreads();

    for (int s = 0; s < TT; s++) {
        // prefetch next step's x
        float xn = 0.f;
        if (lane < 4 && s + 1 < TT) {
            int row = flin ? (TT - 2 - s) : (s + 1);
            xn = P[(size_t)row * 1600 + lane * HH + e];
        }

        const float* cur = hbuf[s & 1];
        float* nxt = hbuf[(s + 1) & 1];

        // GEMV: 4 gate rows x 400, weights in regs, h from smem
        float a0 = 0.f, a1 = 0.f, a2 = 0.f, a3 = 0.f;
#pragma unroll
        for (int j = 0; j < 13; j++) {
            float hv = cur[j * 32 + lane];
            a0 += wreg[0][j] * hv;
            a1 += wreg[1][j] * hv;
            a2 += wreg[2][j] * hv;
            a3 += wreg[3][j] * hv;
        }
        // butterfly allreduce (all lanes end with full sums)
#pragma unroll
        for (int d = 16; d > 0; d >>= 1) {
            a0 += __shfl_xor_sync(0xffffffffu, a0, d);
            a1 += __shfl_xor_sync(0xffffffffu, a1, d);
            a2 += __shfl_xor_sync(0xffffffffu, a2, d);
            a3 += __shfl_xor_sync(0xffffffffu, a3, d);
        }

        // lane q (0..3) applies gate-q nonlinearity (others compute junk)
        float zsel = (lane & 2) ? ((lane & 1) ? a3 : a2)
                                : ((lane & 1) ? a1 : a0);
        float z = zsel + xcur;
        float earg = (lane == 2) ? (-2.f * z) : (-z);
        float r = 1.f / (1.f + __expf(earg));
        float nl = (lane == 2) ? (2.f * r - 1.f) : r;   // tanh for g, sigmoid else

        float gi = __shfl_sync(0xffffffffu, nl, 0);
        float gf = __shfl_sync(0xffffffffu, nl, 1);
        float gg = __shfl_sync(0xffffffffu, nl, 2);
        float go = __shfl_sync(0xffffffffu, nl, 3);

        int orow = flout ? (TT - 1 - s) : s;
        if (lane == 0) {
            float c = gf * creg + gi * gg;
            creg = c;
            float th = 2.f / (1.f + __expf(-2.f * c)) - 1.f;
            float h = go * th;
            outbase[(size_t)orow * ld + col + e] = h;   // layer output
            if (s + 1 < TT) {
                nxt[e] = h;                              // own slice locally
                unsigned long long pk =
                    ((unsigned long long)(unsigned)(s + 1) << 32) |
                    (unsigned long long)__float_as_uint(h);
                unsigned long long* dst = hb + (size_t)(s & 1) * HH + e;
                asm volatile("st.relaxed.gpu.global.b64 [%0], %1;"
                             :: "l"(dst), "l"(pk) : "memory");
            }
        }

        // consume: 200 pollers, 2 elements each, both loads in flight
        if (s + 1 < TT && tid < 200 && (tid < k * 4 || tid >= k * 4 + 4)) {
            const unsigned long long* sp = hb + (size_t)(s & 1) * HH + 2 * tid;
            unsigned tgt = (unsigned)(s + 1);
            unsigned long long v0, v1;
            for (;;) {
                asm volatile("ld.relaxed.gpu.global.b64 %0, [%2];\n\t"
                             "ld.relaxed.gpu.global.b64 %1, [%2+8];"
                             : "=l"(v0), "=l"(v1) : "l"(sp) : "memory");
                if ((unsigned)(v0 >> 32) == tgt && (unsigned)(v1 >> 32) == tgt) break;
            }
            nxt[2 * tid]     = __uint_as_float((unsigned)v0);
            nxt[2 * tid + 1] = __uint_as_float((unsigned)v1);
        }
        xcur = xn;
        __syncthreads();   // nxt complete before next GEMV
    }
}

// ---------------- launch ----------------
extern "C" void kernel_launch(void* const* d_in, const int* in_sizes, int n_in,
                              void* d_out, int out_size)
{
    const int*   word_seq   = (const int*)  d_in[0];
    const int*   pos_seq    = (const int*)  d_in[1];
    const int*   seg_ids    = (const int*)  d_in[2];
    const float* chem       = (const float*)d_in[3];
    const float* word_table = (const float*)d_in[4];
    const float* pos_table  = (const float*)d_in[5];
    const float* Ww         = (const float*)d_in[6];
    const float* Wb         = (const float*)d_in[7];
    const float* Wih1f = (const float*)d_in[8];
    const float* Whh1f = (const float*)d_in[9];
    const float* b1f   = (const float*)d_in[10];
    const float* h01f  = (const float*)d_in[11];
    const float* c01f  = (const float*)d_in[12];
    const float* Wih1b = (const float*)d_in[13];
    const float* Whh1b = (const float*)d_in[14];
    const float* b1b   = (const float*)d_in[15];
    const float* h01b  = (const float*)d_in[16];
    const float* c01b  = (const float*)d_in[17];
    const float* Wih2f = (const float*)d_in[18];
    const float* Whh2f = (const float*)d_in[19];
    const float* b2f   = (const float*)d_in[20];
    const float* h02f  = (const float*)d_in[21];
    const float* c02f  = (const float*)d_in[22];
    const float* Wih2b = (const float*)d_in[23];
    const float* Whh2b = (const float*)d_in[24];
    const float* b2b   = (const float*)d_in[25];
    const float* h02b  = (const float*)d_in[26];
    const float* c02b  = (const float*)d_in[27];

    float* out = (float*)d_out;

    float *ef, *l1, *PF, *PB, *meanp; unsigned long long* hb;
    cudaGetSymbolAddress((void**)&ef,    g_ef);
    cudaGetSymbolAddress((void**)&l1,    g_l1);
    cudaGetSymbolAddress((void**)&PF,    g_PF);
    cudaGetSymbolAddress((void**)&PB,    g_PB);
    cudaGetSymbolAddress((void**)&meanp, g_mean);
    cudaGetSymbolAddress((void**)&hb,    g_hb);

    // (0) mean + starts(bsearch) + hb zero
    k_mean<<<TT, 256>>>(chem, seg_ids);

    // (1) wc = tanh(word_e @ Ww.T + Wb) + mean -> ef[:, :768]; z=1 blocks do pos fill
    k_gemm<<<dim3(6, 32, 2), 256>>>(TT, 768, 300,
        word_table, 300, word_seq,
        Ww, Wb, ef, nullptr, nullptr, nullptr,
        868, meanp, 1, pos_seq, pos_table);

    // (2) layer-1 input projections (both directions)
    k_gemm<<<dim3(13, 32, 2), 256>>>(TT, 1600, 868,
        ef, 868, nullptr,
        Wih1f, b1f, PF,
        Wih1b, b1b, PB,
        1600, nullptr, 0, nullptr, nullptr);

    // (3) layer-1 recurrence
    k_lstm<<<2 * KCTA, NT>>>(
        PF, Whh1f, h01f, c01f, l1, 800, 0,   0, 0, hb + 0 * 2 * HH,
        PB, Whh1b, h01b, c01b, l1, 800, 400, 1, 1, hb + 1 * 2 * HH);

    // (4) layer-2 input projections on l1
    k_gemm<<<dim3(13, 32, 2), 256>>>(TT, 1600, 800,
        l1, 800, nullptr,
        Wih2f, b2f, PF,
        Wih2b, b2b, PB,
        1600, nullptr, 0, nullptr, nullptr);

    // (5) layer-2 recurrence
    k_lstm<<<2 * KCTA, NT>>>(
        PF, Whh2f, h02f, c02f, out,                    400, 0, 0, 0, hb + 2 * 2 * HH,
        PB, Whh2b, h02b, c02b, out + (size_t)TT * 400, 400, 0, 1, 0, hb + 3 * 2 * HH);
}